// round 6
// baseline (speedup 1.0000x reference)
#include <cuda_runtime.h>
#include <math.h>

#define NB   512
#define VV   40
#define NF   32
#define EF   4
#define NIN  68      // 2*NF + EF
#define EMB  128
#define MP   3
#define BIG_NEG -1000000.0f
#define EMAX 65536
#define DMAX 32

// ---- scratch (no allocation allowed) ----
__device__ float g_A0[EMAX * EMB];
__device__ float g_M0[EMAX * EMB];
__device__ float g_mem[EMAX * EMB];
__device__ float g_memN[EMAX * EMB];
__device__ float g_U[EMAX * EMB];
__device__ float g_Vv[EMAX * EMB];
__device__ int   g_idx[EMAX * DMAX];
__device__ float g_gs[NB * VV * EMB];

// ---- init: zero mem0, idx = -1 ----
__global__ void k_init(int E, int D) {
    int i = blockIdx.x * blockDim.x + threadIdx.x;
    if (i < E * EMB) g_mem[i] = 0.0f;
    if (i < E * D)   g_idx[i] = -1;
}

// ---- scatter in-edge lists: idx[igeb*D + ige] = eb ----
__global__ void k_scatter(const int* __restrict__ eb, const int* __restrict__ igeb,
                          const int* __restrict__ ige, int M, int D) {
    int i = blockIdx.x * blockDim.x + threadIdx.x;
    if (i < M) g_idx[igeb[i] * D + ige[i]] = eb[i];
}

// ---- pre: e_emb = tanh(e_in @ W_pre + b), then A0/M0 = e_emb @ W_{att,emb}[:128] + b ----
__global__ void k_pre(const float* __restrict__ nodes, const float* __restrict__ edges,
                      const float* __restrict__ W_pre, const float* __restrict__ b_pre,
                      const float* __restrict__ W_att, const float* __restrict__ b_att,
                      const float* __restrict__ W_emb, const float* __restrict__ b_emb,
                      const int* __restrict__ eb_b, const int* __restrict__ eb_n,
                      const int* __restrict__ eb_nb, int E) {
    const int tid = threadIdx.x;
    const int e0 = blockIdx.x * 8;
    __shared__ float s_in[8][NIN];
    __shared__ float s_e[8][EMB];

    for (int t = tid; t < 8 * NIN; t += 128) {
        int m = t / NIN, k = t % NIN;
        int e = e0 + m;
        float v = 0.0f;
        if (e < E) {
            int b = eb_b[e], n = eb_n[e], nb = eb_nb[e];
            if (k < NF)           v = nodes[(b * VV + n)  * NF + k];
            else if (k < 2 * NF)  v = nodes[(b * VV + nb) * NF + (k - NF)];
            else                  v = edges[((b * VV + n) * VV + nb) * EF + (k - 2 * NF)];
        }
        s_in[m][k] = v;
    }
    __syncthreads();

    float acc[8];
    #pragma unroll
    for (int m = 0; m < 8; m++) acc[m] = b_pre[tid];
    for (int k = 0; k < NIN; k++) {
        float w = W_pre[k * EMB + tid];
        #pragma unroll
        for (int m = 0; m < 8; m++) acc[m] += s_in[m][k] * w;
    }
    #pragma unroll
    for (int m = 0; m < 8; m++) s_e[m][tid] = tanhf(acc[m]);
    __syncthreads();

    float a[8], mm[8];
    #pragma unroll
    for (int m = 0; m < 8; m++) { a[m] = b_att[tid]; mm[m] = b_emb[tid]; }
    for (int k = 0; k < EMB; k++) {
        float wa = W_att[k * EMB + tid];
        float we = W_emb[k * EMB + tid];
        #pragma unroll
        for (int m = 0; m < 8; m++) {
            float sv = s_e[m][k];
            a[m]  += sv * wa;
            mm[m] += sv * we;
        }
    }
    #pragma unroll
    for (int m = 0; m < 8; m++) {
        int e = e0 + m;
        if (e < E) {
            g_A0[e * EMB + tid] = a[m];
            g_M0[e * EMB + tid] = mm[m];
        }
    }
}

// ---- per-step GEMM: U = mem @ Wa2, V = mem @ We2  (Wa2/We2 = bottom halves) ----
__global__ void k_gemm(const float* __restrict__ src,
                       const float* __restrict__ Wa2, const float* __restrict__ We2, int E) {
    const int tid = threadIdx.x;
    const int e0 = blockIdx.x * 16;
    __shared__ float s[16][EMB];
    // vectorized fill: 16 rows * 32 float4 = 512 float4
    for (int t = tid; t < 16 * (EMB / 4); t += 128) {
        int m = t >> 5, k4 = t & 31;
        int e = e0 + m;
        float4 v = make_float4(0.f, 0.f, 0.f, 0.f);
        if (e < E) v = ((const float4*)src)[e * (EMB / 4) + k4];
        ((float4*)&s[m][0])[k4] = v;
    }
    __syncthreads();
    float aU[16], aV[16];
    #pragma unroll
    for (int m = 0; m < 16; m++) { aU[m] = 0.0f; aV[m] = 0.0f; }
    for (int k = 0; k < EMB; k++) {
        float wa = Wa2[k * EMB + tid];
        float we = We2[k * EMB + tid];
        #pragma unroll
        for (int m = 0; m < 16; m++) {
            float sv = s[m][k];
            aU[m] += sv * wa;
            aV[m] += sv * we;
        }
    }
    #pragma unroll
    for (int m = 0; m < 16; m++) {
        int e = e0 + m;
        if (e < E) {
            g_U[e * EMB + tid]  = aU[m];
            g_Vv[e * EMB + tid] = aV[m];
        }
    }
}

// ---- per-step combine: per-channel softmax over in-edges, weighted tanh sum ----
__global__ void k_combine(float* __restrict__ dst, int D, int E) {
    const int e = blockIdx.x;
    const int tid = threadIdx.x;
    __shared__ int js[DMAX];
    if (tid < D) js[tid] = g_idx[e * D + tid];
    __syncthreads();

    float a0 = g_A0[e * EMB + tid];
    float m0 = g_M0[e * EMB + tid];

    float mx = -1e30f;
    int cnt = 0;
    for (int d = 0; d < D; d++) {
        int j = js[d];
        if (j >= 0) {
            cnt++;
            float l = a0 + g_U[j * EMB + tid];
            mx = fmaxf(mx, l);
        }
    }
    float out;
    if (cnt == 0) {
        out = tanhf(m0);   // all-masked: uniform softmax of identical msg rows
    } else {
        float ssum = 0.0f, acc = 0.0f;
        for (int d = 0; d < D; d++) {
            int j = js[d];
            if (j >= 0) {
                float w = expf(a0 + g_U[j * EMB + tid] - mx);
                ssum += w;
                acc  += w * tanhf(m0 + g_Vv[j * EMB + tid]);
            }
        }
        out = acc / ssum;
    }
    dst[e * EMB + tid] = out;
}

// ---- deterministic segment sum: edges sorted by (b, n); binary-search range ----
__global__ void k_segsum(const float* __restrict__ mem,
                         const int* __restrict__ eb_b, const int* __restrict__ eb_n, int E) {
    const int node = blockIdx.x;          // 0 .. NB*VV-1
    const int tid = threadIdx.x;
    __shared__ int s_lo, s_hi;
    if (tid == 0) {
        int lo = 0, hi = E;
        while (lo < hi) {
            int mid = (lo + hi) >> 1;
            int key = eb_b[mid] * VV + eb_n[mid];
            if (key < node) lo = mid + 1; else hi = mid;
        }
        s_lo = lo;
        int lo2 = lo, hi2 = E;
        while (lo2 < hi2) {
            int mid = (lo2 + hi2) >> 1;
            int key = eb_b[mid] * VV + eb_n[mid];
            if (key < node + 1) lo2 = mid + 1; else hi2 = mid;
        }
        s_hi = lo2;
    }
    __syncthreads();
    float acc = 0.0f;
    for (int e = s_lo; e < s_hi; e++) acc += mem[e * EMB + tid];
    g_gs[node * EMB + tid] = acc;
}

// ---- readout: graph attention over V nodes (online softmax), then W_out ----
__global__ void k_readout(const float* __restrict__ node_mask,
                          const float* __restrict__ Wg_att, const float* __restrict__ bg_att,
                          const float* __restrict__ Wg_emb, const float* __restrict__ bg_emb,
                          const float* __restrict__ W_out,  const float* __restrict__ b_out,
                          float* __restrict__ out) {
    const int n = blockIdx.x;
    const int tid = threadIdx.x;
    __shared__ float g[VV][EMB];
    __shared__ float ge[EMB];
    for (int t = tid; t < VV * (EMB / 4); t += 128) {
        int v = t / (EMB / 4), k4 = t % (EMB / 4);
        ((float4*)&g[v][0])[k4] = ((const float4*)(g_gs + (size_t)n * VV * EMB))[v * (EMB / 4) + k4];
    }
    __syncthreads();

    float mx = -1e30f, ssum = 0.0f, acc = 0.0f;
    for (int v = 0; v < VV; v++) {
        float l = bg_att[tid], m = bg_emb[tid];
        for (int k = 0; k < EMB; k++) {
            float gv = g[v][k];
            l += gv * (Wg_att[k * EMB + tid] + Wg_att[(EMB + k) * EMB + tid]);
            m += gv * Wg_emb[k * EMB + tid];
        }
        l += (1.0f - node_mask[n * VV + v]) * BIG_NEG;
        m = tanhf(m);
        float nmx = fmaxf(mx, l);
        float sc = expf(mx - nmx);
        float w  = expf(l - nmx);
        ssum = ssum * sc + w;
        acc  = acc  * sc + w * m;
        mx = nmx;
    }
    ge[tid] = acc / ssum;
    __syncthreads();

    float o = b_out[tid];
    for (int k = 0; k < EMB; k++) o += ge[k] * W_out[k * EMB + tid];
    out[n * EMB + tid] = o;
}

extern "C" void kernel_launch(void* const* d_in, const int* in_sizes, int n_in,
                              void* d_out, int out_size) {
    const float* nodes     = (const float*)d_in[0];
    const float* edges     = (const float*)d_in[1];
    const float* W_pre     = (const float*)d_in[2];
    const float* b_pre     = (const float*)d_in[3];
    const float* W_att     = (const float*)d_in[4];
    const float* b_att     = (const float*)d_in[5];
    const float* W_emb     = (const float*)d_in[6];
    const float* b_emb     = (const float*)d_in[7];
    const float* Wg_att    = (const float*)d_in[8];
    const float* bg_att    = (const float*)d_in[9];
    const float* Wg_emb    = (const float*)d_in[10];
    const float* bg_emb    = (const float*)d_in[11];
    const float* W_out     = (const float*)d_in[12];
    const float* b_out     = (const float*)d_in[13];
    // d_in[14] ingoing_mask (implied by g_idx), d_in[15] node_mask
    const float* node_mask = (const float*)d_in[15];
    const int*   eb_b      = (const int*)d_in[16];
    const int*   eb_n      = (const int*)d_in[17];
    const int*   eb_nb     = (const int*)d_in[18];
    const int*   in_eb     = (const int*)d_in[19];
    const int*   in_igeb   = (const int*)d_in[20];
    const int*   in_ige    = (const int*)d_in[21];

    const int E = in_sizes[16];
    const int D = in_sizes[14] / E;
    const int M = in_sizes[19];

    float *memA, *memB;
    cudaGetSymbolAddress((void**)&memA, g_mem);
    cudaGetSymbolAddress((void**)&memB, g_memN);

    int initN = E * EMB;
    if (E * D > initN) initN = E * D;
    k_init<<<(initN + 255) / 256, 256>>>(E, D);
    k_scatter<<<(M + 255) / 256, 256>>>(in_eb, in_igeb, in_ige, M, D);
    k_pre<<<(E + 7) / 8, 128>>>(nodes, edges, W_pre, b_pre, W_att, b_att,
                                W_emb, b_emb, eb_b, eb_n, eb_nb, E);

    const float* Wa2 = W_att + EMB * EMB;
    const float* We2 = W_emb + EMB * EMB;
    float* src = memA;
    float* dst = memB;
    for (int s = 0; s < MP; s++) {
        k_gemm<<<(E + 15) / 16, 128>>>(src, Wa2, We2, E);
        k_combine<<<E, 128>>>(dst, D, E);
        float* t = src; src = dst; dst = t;
    }

    k_segsum<<<NB * VV, 128>>>(src, eb_b, eb_n, E);
    k_readout<<<NB, 128>>>(node_mask, Wg_att, bg_att, Wg_emb, bg_emb,
                           W_out, b_out, (float*)d_out);
}

// round 7
// speedup vs baseline: 2.2861x; 2.2861x over previous
#include <cuda_runtime.h>
#include <math.h>

#define NB    512
#define VV    40
#define NODES (NB * VV)      // 20480
#define NF    32
#define EF    4
#define NIN   68             // 2*NF + EF
#define EMB   128
#define BIG_NEG -1000000.0f
#define EMAX  65536
#define DMAX  32

// ---- scratch (no allocation allowed) ----
__device__ float  g_M0[EMAX * EMB];
__device__ float  g_mem[EMAX * EMB];
__device__ float  g_memN[EMAX * EMB];
__device__ float2 g_UV[EMAX * EMB];     // (exp(U), V) per edge-channel; reused as (L, tanhT) in readout
__device__ int    g_idx[EMAX * DMAX];
__device__ float  g_gs[NODES * EMB];
__device__ int    g_seg[NODES + 1];
__device__ float2 g_W2[EMB * EMB];      // packed (Wa2, We2) bottom halves
__device__ float2 g_WG[EMB * EMB];      // packed (Wg_att[:128]+Wg_att[128:], Wg_emb)

// ---- init in-edge index table to -1 ----
__global__ void k_initidx(int n) {
    int i = blockIdx.x * blockDim.x + threadIdx.x;
    if (i < n) g_idx[i] = -1;
}

// ---- scatter in-edge lists: idx[igeb*D + ige] = eb ----
__global__ void k_scatter(const int* __restrict__ eb, const int* __restrict__ igeb,
                          const int* __restrict__ ige, int M, int D) {
    int i = blockIdx.x * blockDim.x + threadIdx.x;
    if (i < M) g_idx[igeb[i] * D + ige[i]] = eb[i];
}

// ---- pack weight pairs once per launch ----
__global__ void k_packw(const float* __restrict__ W_att, const float* __restrict__ W_emb,
                        const float* __restrict__ Wg_att, const float* __restrict__ Wg_emb) {
    int k = blockIdx.x, c = threadIdx.x;
    g_W2[k * EMB + c] = make_float2(W_att[(EMB + k) * EMB + c], W_emb[(EMB + k) * EMB + c]);
    g_WG[k * EMB + c] = make_float2(Wg_att[k * EMB + c] + Wg_att[(EMB + k) * EMB + c],
                                    Wg_emb[k * EMB + c]);
}

// ---- pre: e_emb = tanh(e_in @ W_pre + b_pre); M0 = e_emb @ W_emb[:128] + b_emb;
//      mem1 = tanh(M0)  (step-1 closed form, mem0 == 0) ----
__global__ void k_pre(const float* __restrict__ nodes, const float* __restrict__ edges,
                      const float* __restrict__ W_pre, const float* __restrict__ b_pre,
                      const float* __restrict__ W_emb, const float* __restrict__ b_emb,
                      const int* __restrict__ eb_b, const int* __restrict__ eb_n,
                      const int* __restrict__ eb_nb, int E) {
    const int tid = threadIdx.x;
    const int e0 = blockIdx.x * 16;
    __shared__ float s_in[16][NIN];
    __shared__ float s_e[16][EMB];
    __shared__ int   s_o1[16], s_o2[16], s_o3[16];

    if (tid < 16) {
        int e = e0 + tid;
        if (e < E) {
            int b = eb_b[e], n = eb_n[e], nb = eb_nb[e];
            s_o1[tid] = (b * VV + n)  * NF;
            s_o2[tid] = (b * VV + nb) * NF;
            s_o3[tid] = ((b * VV + n) * VV + nb) * EF;
        } else { s_o1[tid] = -1; }
    }
    __syncthreads();

    for (int t = tid; t < 16 * NIN; t += 128) {
        int m = t / NIN, k = t - m * NIN;
        float v = 0.0f;
        if (s_o1[m] >= 0) {
            if (k < NF)          v = nodes[s_o1[m] + k];
            else if (k < 2 * NF) v = nodes[s_o2[m] + (k - NF)];
            else                 v = edges[s_o3[m] + (k - 2 * NF)];
        }
        s_in[m][k] = v;
    }
    __syncthreads();

    float acc[16];
    #pragma unroll
    for (int m = 0; m < 16; m++) acc[m] = b_pre[tid];
    for (int k = 0; k < NIN; k++) {
        float w = W_pre[k * EMB + tid];
        #pragma unroll
        for (int m = 0; m < 16; m++) acc[m] += s_in[m][k] * w;
    }
    #pragma unroll
    for (int m = 0; m < 16; m++) s_e[m][tid] = tanhf(acc[m]);
    __syncthreads();

    float mm[16];
    #pragma unroll
    for (int m = 0; m < 16; m++) mm[m] = b_emb[tid];
    #pragma unroll 4
    for (int k = 0; k < EMB; k++) {
        float we = W_emb[k * EMB + tid];
        #pragma unroll
        for (int m = 0; m < 16; m++) mm[m] += s_e[m][k] * we;
    }
    #pragma unroll
    for (int m = 0; m < 16; m++) {
        int e = e0 + m;
        if (e < E) {
            g_M0[e * EMB + tid]  = mm[m];
            g_mem[e * EMB + tid] = tanhf(mm[m]);
        }
    }
}

// ---- per-step GEMM: (expU, V) = (exp(mem@Wa2), mem@We2), packed float2 ----
__global__ void k_gemm(const float* __restrict__ src, int E) {
    const int tid = threadIdx.x;
    const int e0 = blockIdx.x * 16;
    __shared__ float s[16][EMB];
    for (int t = tid; t < 16 * (EMB / 4); t += 128) {
        int m = t >> 5, k4 = t & 31;
        int e = e0 + m;
        float4 v = make_float4(0.f, 0.f, 0.f, 0.f);
        if (e < E) v = ((const float4*)src)[e * (EMB / 4) + k4];
        ((float4*)&s[m][0])[k4] = v;
    }
    __syncthreads();
    float aU[16], aV[16];
    #pragma unroll
    for (int m = 0; m < 16; m++) { aU[m] = 0.0f; aV[m] = 0.0f; }
    #pragma unroll 4
    for (int k = 0; k < EMB; k++) {
        float2 w = g_W2[k * EMB + tid];
        #pragma unroll
        for (int m = 0; m < 16; m++) {
            float sv = s[m][k];
            aU[m] += sv * w.x;
            aV[m] += sv * w.y;
        }
    }
    #pragma unroll
    for (int m = 0; m < 16; m++) {
        int e = e0 + m;
        if (e < E) g_UV[e * EMB + tid] = make_float2(expf(aU[m]), aV[m]);
    }
}

// ---- per-step combine: single pass, exp precomputed, a0 cancelled ----
__global__ void k_combine(float* __restrict__ dst, int D, int E) {
    const int e = blockIdx.x;
    const int tid = threadIdx.x;
    __shared__ int js[DMAX];
    if (tid < D) js[tid] = g_idx[e * D + tid];
    __syncthreads();

    float m0 = g_M0[e * EMB + tid];
    float ssum = 0.0f, acc = 0.0f;
    int cnt = 0;
    for (int d = 0; d < D; d++) {
        int j = js[d];
        if (j >= 0) {
            float2 uv = g_UV[j * EMB + tid];
            ssum += uv.x;
            acc  += uv.x * tanhf(m0 + uv.y);
            cnt++;
        }
    }
    dst[e * EMB + tid] = cnt ? (acc / ssum) : tanhf(m0);
}

// ---- segment boundaries (edges sorted by (b,n) key) ----
__global__ void k_segbounds(const int* __restrict__ eb_b, const int* __restrict__ eb_n, int E) {
    int e = blockIdx.x * blockDim.x + threadIdx.x;
    if (e >= E) return;
    int k  = eb_b[e] * VV + eb_n[e];
    int kp = (e == 0) ? -1 : (eb_b[e - 1] * VV + eb_n[e - 1]);
    for (int v = kp + 1; v <= k; v++) g_seg[v] = e;
    if (e == E - 1) for (int v = k + 1; v <= NODES; v++) g_seg[v] = E;
}

// ---- segment sum using precomputed bounds ----
__global__ void k_segsum(const float* __restrict__ mem) {
    const int node = blockIdx.x;
    const int tid = threadIdx.x;
    int lo = g_seg[node], hi = g_seg[node + 1];
    float acc = 0.0f;
    for (int e = lo; e < hi; e++) acc += mem[e * EMB + tid];
    g_gs[node * EMB + tid] = acc;
}

// ---- readout GEMM: (L, tanhT) per node row, packed float2 ----
__global__ void k_gemm2(const float* __restrict__ bg_att, const float* __restrict__ bg_emb) {
    const int tid = threadIdx.x;
    const int r0 = blockIdx.x * 16;
    __shared__ float s[16][EMB];
    for (int t = tid; t < 16 * (EMB / 4); t += 128) {
        int m = t >> 5, k4 = t & 31;
        ((float4*)&s[m][0])[k4] = ((const float4*)g_gs)[(r0 + m) * (EMB / 4) + k4];
    }
    __syncthreads();
    float aL[16], aT[16];
    float bl = bg_att[tid], bt = bg_emb[tid];
    #pragma unroll
    for (int m = 0; m < 16; m++) { aL[m] = bl; aT[m] = bt; }
    #pragma unroll 4
    for (int k = 0; k < EMB; k++) {
        float2 w = g_WG[k * EMB + tid];
        #pragma unroll
        for (int m = 0; m < 16; m++) {
            float sv = s[m][k];
            aL[m] += sv * w.x;
            aT[m] += sv * w.y;
        }
    }
    #pragma unroll
    for (int m = 0; m < 16; m++)
        g_UV[(r0 + m) * EMB + tid] = make_float2(aL[m], tanhf(aT[m]));
}

// ---- readout softmax over V nodes + final projection ----
__global__ void k_rsoft(const float* __restrict__ node_mask,
                        const float* __restrict__ W_out, const float* __restrict__ b_out,
                        float* __restrict__ out) {
    const int n = blockIdx.x;
    const int tid = threadIdx.x;
    __shared__ float s_msk[VV];
    __shared__ float ge[EMB];
    __shared__ int   s_any;
    if (tid == 0) s_any = 0;
    __syncthreads();
    if (tid < VV) {
        s_msk[tid] = node_mask[n * VV + tid];
        if (s_msk[tid] > 0.5f) atomicOr(&s_any, 1);
    }
    __syncthreads();
    const int any = s_any;

    const float2* LT = g_UV + (size_t)n * VV * EMB;
    float mx = -1e30f;
    for (int v = 0; v < VV; v++) {
        if (!any || s_msk[v] > 0.5f) {
            float l = LT[v * EMB + tid].x;
            mx = fmaxf(mx, l);
        }
    }
    float ssum = 0.0f, acc = 0.0f;
    for (int v = 0; v < VV; v++) {
        if (!any || s_msk[v] > 0.5f) {
            float2 lt = LT[v * EMB + tid];
            float w = expf(lt.x - mx);
            ssum += w;
            acc  += w * lt.y;
        }
    }
    ge[tid] = acc / ssum;
    __syncthreads();

    float o = b_out[tid];
    #pragma unroll 4
    for (int k = 0; k < EMB; k++) o += ge[k] * W_out[k * EMB + tid];
    out[n * EMB + tid] = o;
}

extern "C" void kernel_launch(void* const* d_in, const int* in_sizes, int n_in,
                              void* d_out, int out_size) {
    const float* nodes     = (const float*)d_in[0];
    const float* edges     = (const float*)d_in[1];
    const float* W_pre     = (const float*)d_in[2];
    const float* b_pre     = (const float*)d_in[3];
    const float* W_att     = (const float*)d_in[4];
    const float* W_emb     = (const float*)d_in[6];
    const float* b_emb     = (const float*)d_in[7];
    const float* Wg_att    = (const float*)d_in[8];
    const float* bg_att    = (const float*)d_in[9];
    const float* Wg_emb    = (const float*)d_in[10];
    const float* bg_emb    = (const float*)d_in[11];
    const float* W_out     = (const float*)d_in[12];
    const float* b_out     = (const float*)d_in[13];
    const float* node_mask = (const float*)d_in[15];
    const int*   eb_b      = (const int*)d_in[16];
    const int*   eb_n      = (const int*)d_in[17];
    const int*   eb_nb     = (const int*)d_in[18];
    const int*   in_eb     = (const int*)d_in[19];
    const int*   in_igeb   = (const int*)d_in[20];
    const int*   in_ige    = (const int*)d_in[21];

    const int E = in_sizes[16];
    const int D = in_sizes[14] / E;
    const int M = in_sizes[19];

    float *memA, *memB;
    cudaGetSymbolAddress((void**)&memA, g_mem);
    cudaGetSymbolAddress((void**)&memB, g_memN);

    k_initidx<<<(E * D + 255) / 256, 256>>>(E * D);
    k_scatter<<<(M + 255) / 256, 256>>>(in_eb, in_igeb, in_ige, M, D);
    k_packw<<<EMB, EMB>>>(W_att, W_emb, Wg_att, Wg_emb);
    k_pre<<<(E + 15) / 16, 128>>>(nodes, edges, W_pre, b_pre, W_emb, b_emb,
                                  eb_b, eb_n, eb_nb, E);

    // step 1 done analytically in k_pre (mem1 = tanh(M0)); run steps 2..3
    float* src = memA;
    float* dst = memB;
    for (int s = 0; s < 2; s++) {
        k_gemm<<<(E + 15) / 16, 128>>>(src, E);
        k_combine<<<E, 128>>>(dst, D, E);
        float* t = src; src = dst; dst = t;
    }

    k_segbounds<<<(E + 255) / 256, 256>>>(eb_b, eb_n, E);
    k_segsum<<<NODES, 128>>>(src);
    k_gemm2<<<NODES / 16, 128>>>(bg_att, bg_emb);
    k_rsoft<<<NB, 128>>>(node_mask, W_out, b_out, (float*)d_out);
}

// round 9
// speedup vs baseline: 2.7132x; 1.1868x over previous
#include <cuda_runtime.h>
#include <math.h>

#define NB    512
#define VV    40
#define NODES (NB * VV)      // 20480
#define NF    32
#define EF    4
#define NIN   68             // 2*NF + EF
#define EMB   128
#define BIG_NEG -1000000.0f
#define EMAX  65536
#define DMAX  32

// ---- scratch (no allocation allowed) ----
__device__ float  g_M0[EMAX * EMB];
__device__ float  g_mem[EMAX * EMB];
__device__ float  g_memN[EMAX * EMB];
__device__ float2 g_UV[EMAX * EMB];     // (exp(U), V) per edge-channel; reused as (L, tanhT) in readout
__device__ int    g_idx[EMAX * DMAX];
__device__ float  g_gs[NODES * EMB];
__device__ int    g_seg[NODES + 1];
__device__ float2 g_W2[EMB * EMB];      // packed (Wa2, We2) bottom halves
__device__ float2 g_WG[EMB * EMB];      // packed (Wg_att[:128]+Wg_att[128:], Wg_emb)

// ---- init in-edge index table to -1 ----
__global__ void k_initidx(int n) {
    int i = blockIdx.x * blockDim.x + threadIdx.x;
    if (i < n) g_idx[i] = -1;
}

// ---- scatter in-edge lists: idx[igeb*D + ige] = eb ----
__global__ void k_scatter(const int* __restrict__ eb, const int* __restrict__ igeb,
                          const int* __restrict__ ige, int M, int D) {
    int i = blockIdx.x * blockDim.x + threadIdx.x;
    if (i < M) g_idx[igeb[i] * D + ige[i]] = eb[i];
}

// ---- pack weight pairs once per launch ----
__global__ void k_packw(const float* __restrict__ W_att, const float* __restrict__ W_emb,
                        const float* __restrict__ Wg_att, const float* __restrict__ Wg_emb) {
    int k = blockIdx.x, c = threadIdx.x;
    g_W2[k * EMB + c] = make_float2(W_att[(EMB + k) * EMB + c], W_emb[(EMB + k) * EMB + c]);
    g_WG[k * EMB + c] = make_float2(Wg_att[k * EMB + c] + Wg_att[(EMB + k) * EMB + c],
                                    Wg_emb[k * EMB + c]);
}

// ---- pre: e_emb = tanh(e_in @ W_pre + b_pre); M0 = e_emb @ W_emb[:128] + b_emb;
//      mem1 = tanh(M0)  (step-1 closed form, mem0 == 0) ----
__global__ void k_pre(const float* __restrict__ nodes, const float* __restrict__ edges,
                      const float* __restrict__ W_pre, const float* __restrict__ b_pre,
                      const float* __restrict__ W_emb, const float* __restrict__ b_emb,
                      const int* __restrict__ eb_b, const int* __restrict__ eb_n,
                      const int* __restrict__ eb_nb, int E) {
    const int tid = threadIdx.x;
    const int e0 = blockIdx.x * 16;
    __shared__ __align__(16) float s_in[16][NIN];   // 68 floats = 272B stride (16B mult.)
    __shared__ __align__(16) float s_e[16][EMB];
    __shared__ int   s_o1[16], s_o2[16], s_o3[16];

    if (tid < 16) {
        int e = e0 + tid;
        if (e < E) {
            int b = eb_b[e], n = eb_n[e], nb = eb_nb[e];
            s_o1[tid] = (b * VV + n)  * NF;
            s_o2[tid] = (b * VV + nb) * NF;
            s_o3[tid] = ((b * VV + n) * VV + nb) * EF;
        } else { s_o1[tid] = -1; }
    }
    __syncthreads();

    for (int t = tid; t < 16 * NIN; t += 128) {
        int m = t / NIN, k = t - m * NIN;
        float v = 0.0f;
        if (s_o1[m] >= 0) {
            if (k < NF)          v = nodes[s_o1[m] + k];
            else if (k < 2 * NF) v = nodes[s_o2[m] + (k - NF)];
            else                 v = edges[s_o3[m] + (k - 2 * NF)];
        }
        s_in[m][k] = v;
    }
    __syncthreads();

    float acc[16];
    #pragma unroll
    for (int m = 0; m < 16; m++) acc[m] = b_pre[tid];
    #pragma unroll 1
    for (int k = 0; k < NIN; k += 4) {          // 68 = 17*4
        float w0 = W_pre[(k + 0) * EMB + tid];
        float w1 = W_pre[(k + 1) * EMB + tid];
        float w2 = W_pre[(k + 2) * EMB + tid];
        float w3 = W_pre[(k + 3) * EMB + tid];
        #pragma unroll
        for (int m = 0; m < 16; m++) {
            float4 sv = *(const float4*)&s_in[m][k];
            acc[m] += sv.x * w0 + sv.y * w1 + sv.z * w2 + sv.w * w3;
        }
    }
    #pragma unroll
    for (int m = 0; m < 16; m++) s_e[m][tid] = tanhf(acc[m]);
    __syncthreads();

    float mm[16];
    #pragma unroll
    for (int m = 0; m < 16; m++) mm[m] = b_emb[tid];
    #pragma unroll 1
    for (int k = 0; k < EMB; k += 4) {
        float w0 = W_emb[(k + 0) * EMB + tid];
        float w1 = W_emb[(k + 1) * EMB + tid];
        float w2 = W_emb[(k + 2) * EMB + tid];
        float w3 = W_emb[(k + 3) * EMB + tid];
        #pragma unroll
        for (int m = 0; m < 16; m++) {
            float4 sv = *(const float4*)&s_e[m][k];
            mm[m] += sv.x * w0 + sv.y * w1 + sv.z * w2 + sv.w * w3;
        }
    }
    #pragma unroll
    for (int m = 0; m < 16; m++) {
        int e = e0 + m;
        if (e < E) {
            g_M0[e * EMB + tid]  = mm[m];
            g_mem[e * EMB + tid] = tanhf(mm[m]);
        }
    }
}

// ---- per-step GEMM: (expU, V) = (exp(mem@Wa2), mem@We2), packed float2 ----
__global__ void k_gemm(const float* __restrict__ src, int E) {
    const int tid = threadIdx.x;
    const int e0 = blockIdx.x * 16;
    __shared__ __align__(16) float s[16][EMB];
    for (int t = tid; t < 16 * (EMB / 4); t += 128) {
        int m = t >> 5, k4 = t & 31;
        int e = e0 + m;
        float4 v = make_float4(0.f, 0.f, 0.f, 0.f);
        if (e < E) v = ((const float4*)src)[e * (EMB / 4) + k4];
        ((float4*)&s[m][0])[k4] = v;
    }
    __syncthreads();
    float aU[16], aV[16];
    #pragma unroll
    for (int m = 0; m < 16; m++) { aU[m] = 0.0f; aV[m] = 0.0f; }
    #pragma unroll 1
    for (int k = 0; k < EMB; k += 4) {
        float2 wa = g_W2[(k + 0) * EMB + tid];
        float2 wb = g_W2[(k + 1) * EMB + tid];
        float2 wc = g_W2[(k + 2) * EMB + tid];
        float2 wd = g_W2[(k + 3) * EMB + tid];
        #pragma unroll
        for (int m = 0; m < 16; m++) {
            float4 sv = *(const float4*)&s[m][k];
            aU[m] += sv.x * wa.x + sv.y * wb.x + sv.z * wc.x + sv.w * wd.x;
            aV[m] += sv.x * wa.y + sv.y * wb.y + sv.z * wc.y + sv.w * wd.y;
        }
    }
    #pragma unroll
    for (int m = 0; m < 16; m++) {
        int e = e0 + m;
        if (e < E) g_UV[e * EMB + tid] = make_float2(expf(aU[m]), aV[m]);
    }
}

// ---- per-step combine: single pass, exp precomputed, a0 cancelled ----
__global__ void k_combine(float* __restrict__ dst, int D, int E) {
    const int e = blockIdx.x;
    const int tid = threadIdx.x;
    __shared__ int js[DMAX];
    if (tid < D) js[tid] = g_idx[e * D + tid];
    __syncthreads();

    float m0 = g_M0[e * EMB + tid];
    float ssum = 0.0f, acc = 0.0f;
    int cnt = 0;
    for (int d = 0; d < D; d++) {
        int j = js[d];
        if (j >= 0) {
            float2 uv = g_UV[j * EMB + tid];
            ssum += uv.x;
            acc  += uv.x * tanhf(m0 + uv.y);
            cnt++;
        }
    }
    dst[e * EMB + tid] = cnt ? (acc / ssum) : tanhf(m0);
}

// ---- segment boundaries (edges sorted by (b,n) key) ----
__global__ void k_segbounds(const int* __restrict__ eb_b, const int* __restrict__ eb_n, int E) {
    int e = blockIdx.x * blockDim.x + threadIdx.x;
    if (e >= E) return;
    int k  = eb_b[e] * VV + eb_n[e];
    int kp = (e == 0) ? -1 : (eb_b[e - 1] * VV + eb_n[e - 1]);
    for (int v = kp + 1; v <= k; v++) g_seg[v] = e;
    if (e == E - 1) for (int v = k + 1; v <= NODES; v++) g_seg[v] = E;
}

// ---- segment sum using precomputed bounds ----
__global__ void k_segsum(const float* __restrict__ mem) {
    const int node = blockIdx.x;
    const int tid = threadIdx.x;
    int lo = g_seg[node], hi = g_seg[node + 1];
    float acc = 0.0f;
    for (int e = lo; e < hi; e++) acc += mem[e * EMB + tid];
    g_gs[node * EMB + tid] = acc;
}

// ---- readout GEMM: (L, tanhT) per node row, packed float2 ----
__global__ void k_gemm2(const float* __restrict__ bg_att, const float* __restrict__ bg_emb) {
    const int tid = threadIdx.x;
    const int r0 = blockIdx.x * 16;
    __shared__ __align__(16) float s[16][EMB];
    for (int t = tid; t < 16 * (EMB / 4); t += 128) {
        int m = t >> 5, k4 = t & 31;
        ((float4*)&s[m][0])[k4] = ((const float4*)g_gs)[(r0 + m) * (EMB / 4) + k4];
    }
    __syncthreads();
    float aL[16], aT[16];
    float bl = bg_att[tid], bt = bg_emb[tid];
    #pragma unroll
    for (int m = 0; m < 16; m++) { aL[m] = bl; aT[m] = bt; }
    #pragma unroll 1
    for (int k = 0; k < EMB; k += 4) {
        float2 wa = g_WG[(k + 0) * EMB + tid];
        float2 wb = g_WG[(k + 1) * EMB + tid];
        float2 wc = g_WG[(k + 2) * EMB + tid];
        float2 wd = g_WG[(k + 3) * EMB + tid];
        #pragma unroll
        for (int m = 0; m < 16; m++) {
            float4 sv = *(const float4*)&s[m][k];
            aL[m] += sv.x * wa.x + sv.y * wb.x + sv.z * wc.x + sv.w * wd.x;
            aT[m] += sv.x * wa.y + sv.y * wb.y + sv.z * wc.y + sv.w * wd.y;
        }
    }
    #pragma unroll
    for (int m = 0; m < 16; m++)
        g_UV[(r0 + m) * EMB + tid] = make_float2(aL[m], tanhf(aT[m]));
}

// ---- readout softmax over V nodes + final projection ----
__global__ void k_rsoft(const float* __restrict__ node_mask,
                        const float* __restrict__ W_out, const float* __restrict__ b_out,
                        float* __restrict__ out) {
    const int n = blockIdx.x;
    const int tid = threadIdx.x;
    __shared__ float s_msk[VV];
    __shared__ float ge[EMB];
    __shared__ int   s_any;
    if (tid == 0) s_any = 0;
    __syncthreads();
    if (tid < VV) {
        s_msk[tid] = node_mask[n * VV + tid];
        if (s_msk[tid] > 0.5f) atomicOr(&s_any, 1);
    }
    __syncthreads();
    const int any = s_any;

    const float2* LT = g_UV + (size_t)n * VV * EMB;
    float mx = -1e30f;
    for (int v = 0; v < VV; v++) {
        if (!any || s_msk[v] > 0.5f) {
            float l = LT[v * EMB + tid].x;
            mx = fmaxf(mx, l);
        }
    }
    float ssum = 0.0f, acc = 0.0f;
    for (int v = 0; v < VV; v++) {
        if (!any || s_msk[v] > 0.5f) {
            float2 lt = LT[v * EMB + tid];
            float w = expf(lt.x - mx);
            ssum += w;
            acc  += w * lt.y;
        }
    }
    ge[tid] = acc / ssum;
    __syncthreads();

    float o = b_out[tid];
    #pragma unroll 4
    for (int k = 0; k < EMB; k++) o += ge[k] * W_out[k * EMB + tid];
    out[n * EMB + tid] = o;
}

extern "C" void kernel_launch(void* const* d_in, const int* in_sizes, int n_in,
                              void* d_out, int out_size) {
    const float* nodes     = (const float*)d_in[0];
    const float* edges     = (const float*)d_in[1];
    const float* W_pre     = (const float*)d_in[2];
    const float* b_pre     = (const float*)d_in[3];
    const float* W_att     = (const float*)d_in[4];
    const float* W_emb     = (const float*)d_in[6];
    const float* b_emb     = (const float*)d_in[7];
    const float* Wg_att    = (const float*)d_in[8];
    const float* bg_att    = (const float*)d_in[9];
    const float* Wg_emb    = (const float*)d_in[10];
    const float* bg_emb    = (const float*)d_in[11];
    const float* W_out     = (const float*)d_in[12];
    const float* b_out     = (const float*)d_in[13];
    const float* node_mask = (const float*)d_in[15];
    const int*   eb_b      = (const int*)d_in[16];
    const int*   eb_n      = (const int*)d_in[17];
    const int*   eb_nb     = (const int*)d_in[18];
    const int*   in_eb     = (const int*)d_in[19];
    const int*   in_igeb   = (const int*)d_in[20];
    const int*   in_ige    = (const int*)d_in[21];

    const int E = in_sizes[16];
    const int D = in_sizes[14] / E;
    const int M = in_sizes[19];

    float *memA, *memB;
    cudaGetSymbolAddress((void**)&memA, g_mem);
    cudaGetSymbolAddress((void**)&memB, g_memN);

    k_initidx<<<(E * D + 255) / 256, 256>>>(E * D);
    k_scatter<<<(M + 255) / 256, 256>>>(in_eb, in_igeb, in_ige, M, D);
    k_packw<<<EMB, EMB>>>(W_att, W_emb, Wg_att, Wg_emb);
    k_pre<<<(E + 15) / 16, 128>>>(nodes, edges, W_pre, b_pre, W_emb, b_emb,
                                  eb_b, eb_n, eb_nb, E);

    // step 1 done analytically in k_pre (mem1 = tanh(M0)); run steps 2..3
    float* src = memA;
    float* dst = memB;
    for (int s = 0; s < 2; s++) {
        k_gemm<<<(E + 15) / 16, 128>>>(src, E);
        k_combine<<<E, 128>>>(dst, D, E);
        float* t = src; src = dst; dst = t;
    }

    k_segbounds<<<(E + 255) / 256, 256>>>(eb_b, eb_n, E);
    k_segsum<<<NODES, 128>>>(src);
    k_gemm2<<<NODES / 16, 128>>>(bg_att, bg_emb);
    k_rsoft<<<NB, 128>>>(node_mask, W_out, b_out, (float*)d_out);
}

// round 12
// speedup vs baseline: 2.8295x; 1.0429x over previous
#include <cuda_runtime.h>
#include <cuda_bf16.h>
#include <math.h>
#include <stdint.h>

#define NB    512
#define VV    40
#define NODES (NB * VV)      // 20480
#define NF    32
#define EF    4
#define NIN   68             // 2*NF + EF
#define EMB   128
#define BIG_NEG -1000000.0f
#define EMAX  65536
#define DMAX  32

// column-pair index permutation: p = tg + 4h + 8k  ->  j = 2tg + h + 8k
#define PERM(p) ((((p) & 3) << 1) | (((p) >> 2) & 1) | ((p) & ~7))

// ---- scratch (no allocation allowed) ----
__device__ float  g_M0[EMAX * EMB];
__device__ float  g_mem[EMAX * EMB];
__device__ float  g_memN[EMAX * EMB];
__device__ float2 g_UV[EMAX * EMB];     // (expU, V) per edge-ch; (L, tanhT) in readout
__device__ int    g_idx[EMAX * DMAX];
__device__ float  g_gs[NODES * EMB];
__device__ int    g_seg[NODES + 1];
// pre-packed B operands: (hi,lo) bf16-pair u64 per (n, kpair), permuted+swizzled.
// set 0 = msg step [Wa2|We2], set 1 = readout [WGatt_sum|WGemb]
__device__ __align__(16) uint2 g_B[2][256 * 64];

__device__ __forceinline__ uint2 pack_hl(float x0, float x1) {
    __nv_bfloat16 h0 = __float2bfloat16(x0);
    __nv_bfloat16 h1 = __float2bfloat16(x1);
    __nv_bfloat16 l0 = __float2bfloat16(x0 - __bfloat162float(h0));
    __nv_bfloat16 l1 = __float2bfloat16(x1 - __bfloat162float(h1));
    uint32_t hi = (uint32_t)*(uint16_t*)&h0 | ((uint32_t)*(uint16_t*)&h1 << 16);
    uint32_t lo = (uint32_t)*(uint16_t*)&l0 | ((uint32_t)*(uint16_t*)&l1 << 16);
    return make_uint2(hi, lo);
}

__device__ __forceinline__ void mma16816(float* d, uint32_t a0, uint32_t a1,
                                         uint32_t a2, uint32_t a3,
                                         uint32_t b0, uint32_t b1) {
    asm volatile("mma.sync.aligned.m16n8k16.row.col.f32.bf16.bf16.f32 "
                 "{%0,%1,%2,%3}, {%4,%5,%6,%7}, {%8,%9}, {%0,%1,%2,%3};"
                 : "+f"(d[0]), "+f"(d[1]), "+f"(d[2]), "+f"(d[3])
                 : "r"(a0), "r"(a1), "r"(a2), "r"(a3), "r"(b0), "r"(b1));
}

// ---- init in-edge index table to -1 ----
__global__ void k_initidx(int n) {
    int i = blockIdx.x * blockDim.x + threadIdx.x;
    if (i < n) g_idx[i] = -1;
}

// ---- scatter in-edge lists ----
__global__ void k_scatter(const int* __restrict__ eb, const int* __restrict__ igeb,
                          const int* __restrict__ ige, int M, int D) {
    int i = blockIdx.x * blockDim.x + threadIdx.x;
    if (i < M) g_idx[igeb[i] * D + ige[i]] = eb[i];
}

// ---- pack B operands (hi/lo split, permuted + XOR-swizzled) ----
__global__ void k_packb(const float* __restrict__ W_att, const float* __restrict__ W_emb,
                        const float* __restrict__ Wg_att, const float* __restrict__ Wg_emb) {
    int idx = blockIdx.x * 256 + threadIdx.x;   // 2 * 256 * 64 = 32768
    int set = idx >> 14;
    int rem = idx & 16383;
    int n   = rem >> 6;
    int p   = rem & 63;
    int kp  = 2 * p;
    float x0, x1;
    if (set == 0) {
        if (n < 128) {
            x0 = W_att[(128 + kp) * EMB + n];
            x1 = W_att[(129 + kp) * EMB + n];
        } else {
            x0 = W_emb[(128 + kp) * EMB + (n - 128)];
            x1 = W_emb[(129 + kp) * EMB + (n - 128)];
        }
    } else {
        if (n < 128) {
            x0 = Wg_att[kp * EMB + n]       + Wg_att[(128 + kp) * EMB + n];
            x1 = Wg_att[(kp + 1) * EMB + n] + Wg_att[(129 + kp) * EMB + n];
        } else {
            x0 = Wg_emb[kp * EMB + (n - 128)];
            x1 = Wg_emb[(kp + 1) * EMB + (n - 128)];
        }
    }
    g_B[set][n * 64 + (PERM(p) ^ (4 * (n & 7)))] = pack_hl(x0, x1);
}

// ---- pre: e_emb = tanh(e_in @ W_pre + b_pre); M0 = e_emb @ W_emb[:128] + b_emb;
//      mem1 = tanh(M0)  (step-1 closed form, mem0 == 0) ----
__global__ void k_pre(const float* __restrict__ nodes, const float* __restrict__ edges,
                      const float* __restrict__ W_pre, const float* __restrict__ b_pre,
                      const float* __restrict__ W_emb, const float* __restrict__ b_emb,
                      const int* __restrict__ eb_b, const int* __restrict__ eb_n,
                      const int* __restrict__ eb_nb, int E) {
    const int tid = threadIdx.x;
    const int e0 = blockIdx.x * 16;
    __shared__ __align__(16) float s_in[16][NIN];
    __shared__ __align__(16) float s_e[16][EMB];
    __shared__ int   s_o1[16], s_o2[16], s_o3[16];

    if (tid < 16) {
        int e = e0 + tid;
        if (e < E) {
            int b = eb_b[e], n = eb_n[e], nb = eb_nb[e];
            s_o1[tid] = (b * VV + n)  * NF;
            s_o2[tid] = (b * VV + nb) * NF;
            s_o3[tid] = ((b * VV + n) * VV + nb) * EF;
        } else { s_o1[tid] = -1; }
    }
    __syncthreads();

    for (int t = tid; t < 16 * NIN; t += 128) {
        int m = t / NIN, k = t - m * NIN;
        float v = 0.0f;
        if (s_o1[m] >= 0) {
            if (k < NF)          v = nodes[s_o1[m] + k];
            else if (k < 2 * NF) v = nodes[s_o2[m] + (k - NF)];
            else                 v = edges[s_o3[m] + (k - 2 * NF)];
        }
        s_in[m][k] = v;
    }
    __syncthreads();

    float acc[16];
    #pragma unroll
    for (int m = 0; m < 16; m++) acc[m] = b_pre[tid];
    #pragma unroll 1
    for (int k = 0; k < NIN; k += 4) {
        float w0 = W_pre[(k + 0) * EMB + tid];
        float w1 = W_pre[(k + 1) * EMB + tid];
        float w2 = W_pre[(k + 2) * EMB + tid];
        float w3 = W_pre[(k + 3) * EMB + tid];
        #pragma unroll
        for (int m = 0; m < 16; m++) {
            float4 sv = *(const float4*)&s_in[m][k];
            acc[m] += sv.x * w0 + sv.y * w1 + sv.z * w2 + sv.w * w3;
        }
    }
    #pragma unroll
    for (int m = 0; m < 16; m++) s_e[m][tid] = tanhf(acc[m]);
    __syncthreads();

    float mm[16];
    #pragma unroll
    for (int m = 0; m < 16; m++) mm[m] = b_emb[tid];
    #pragma unroll 1
    for (int k = 0; k < EMB; k += 4) {
        float w0 = W_emb[(k + 0) * EMB + tid];
        float w1 = W_emb[(k + 1) * EMB + tid];
        float w2 = W_emb[(k + 2) * EMB + tid];
        float w3 = W_emb[(k + 3) * EMB + tid];
        #pragma unroll
        for (int m = 0; m < 16; m++) {
            float4 sv = *(const float4*)&s_e[m][k];
            mm[m] += sv.x * w0 + sv.y * w1 + sv.z * w2 + sv.w * w3;
        }
    }
    #pragma unroll
    for (int m = 0; m < 16; m++) {
        int e = e0 + m;
        if (e < E) {
            g_M0[e * EMB + tid]  = mm[m];
            g_mem[e * EMB + tid] = tanhf(mm[m]);
        }
    }
}

// ============ tensor-core GEMM: [rows x 128] @ [128 x 256] (split bf16) ======
// mode 0: out[e][c] = (exp(D[e][c]), D[e][c+128])
// mode 1: out[e][c] = (D[e][c]+ba[c], tanh(D[e][c+128]+bb[c]))
#define SMB_BYTES 131072      // B: [256][64] uint2
#define SMA_BYTES 65536       // A: [128][64] uint2
#define SM_TOTAL  (SMB_BYTES + SMA_BYTES)

__global__ __launch_bounds__(256, 1)
void k_gemm_tc(const float* __restrict__ src, const uint2* __restrict__ Bg,
               const float* __restrict__ ba, const float* __restrict__ bb,
               float2* __restrict__ out, int rows, int mode) {
    extern __shared__ __align__(16) char sm[];
    uint2* Bs = (uint2*)sm;                       // [256][64]
    uint2* As = (uint2*)(sm + SMB_BYTES);         // [128][64]
    const int tid = threadIdx.x;
    const int e0 = blockIdx.x * 128;

    // copy pre-swizzled B: 16384 uint2 = 8192 uint4
    {
        const uint4* s = (const uint4*)Bg;
        uint4* d = (uint4*)Bs;
        #pragma unroll 4
        for (int i = tid; i < 8192; i += 256) d[i] = s[i];
    }
    // convert A rows to (hi,lo) pairs, permuted + swizzled
    {
        int row = tid >> 1, half = tid & 1;
        int e = e0 + row;
        int sw = 4 * (row & 7);
        uint2* arow = As + row * 64;
        #pragma unroll 1
        for (int p = half * 32; p < half * 32 + 32; p += 2) {
            float4 f = make_float4(0.f, 0.f, 0.f, 0.f);
            if (e < rows) f = *(const float4*)&src[e * EMB + 2 * p];
            arow[PERM(p) ^ sw]     = pack_hl(f.x, f.y);
            arow[PERM(p + 1) ^ sw] = pack_hl(f.z, f.w);
        }
    }
    __syncthreads();

    const int wid = tid >> 5, lane = tid & 31;
    const int g = lane >> 2, tg = lane & 3;
    const int nU = wid * 16;

    // per-thread bias values (mode 1), cols independent of m-tile
    float ba0[2], ba1[2], bb0[2], bb1[2];
    if (mode == 1) {
        #pragma unroll
        for (int nt = 0; nt < 2; nt++) {
            int c = nU + nt * 8 + tg * 2;
            ba0[nt] = ba[c]; ba1[nt] = ba[c + 1];
            bb0[nt] = bb[c]; bb1[nt] = bb[c + 1];
        }
    }

    #pragma unroll 1
    for (int mt = 0; mt < 8; mt++) {
        float d[4][4];
        #pragma unroll
        for (int a = 0; a < 4; a++)
            #pragma unroll
            for (int b = 0; b < 4; b++) d[a][b] = 0.0f;

        const int rowA = mt * 16 + g;
        #pragma unroll 1
        for (int k = 0; k < 8; k++) {
            int jx = (2 * tg + 8 * k) ^ (4 * g);
            uint4 A1 = *(const uint4*)&As[rowA * 64 + jx];
            uint4 A2 = *(const uint4*)&As[(rowA + 8) * 64 + jx];
            #pragma unroll
            for (int nt = 0; nt < 4; nt++) {
                int n0 = (nt < 2) ? (nU + nt * 8) : (128 + nU + (nt - 2) * 8);
                uint4 Bf = *(const uint4*)&Bs[(n0 + g) * 64 + jx];
                mma16816(d[nt], A1.x, A2.x, A1.z, A2.z, Bf.x, Bf.z);  // hi*hi
                mma16816(d[nt], A1.x, A2.x, A1.z, A2.z, Bf.y, Bf.w);  // hi*lo
                mma16816(d[nt], A1.y, A2.y, A1.w, A2.w, Bf.x, Bf.z);  // lo*hi
            }
        }

        int r0 = e0 + mt * 16 + g, r1 = r0 + 8;
        #pragma unroll
        for (int nt = 0; nt < 2; nt++) {
            int c = nU + nt * 8 + tg * 2;
            float u0 = d[nt][0], u1 = d[nt][1], u2 = d[nt][2], u3 = d[nt][3];
            float v0 = d[nt + 2][0], v1 = d[nt + 2][1], v2 = d[nt + 2][2], v3 = d[nt + 2][3];
            float4 o0, o1;
            if (mode == 0) {
                o0 = make_float4(expf(u0), v0, expf(u1), v1);
                o1 = make_float4(expf(u2), v2, expf(u3), v3);
            } else {
                o0 = make_float4(u0 + ba0[nt], tanhf(v0 + bb0[nt]),
                                 u1 + ba1[nt], tanhf(v1 + bb1[nt]));
                o1 = make_float4(u2 + ba0[nt], tanhf(v2 + bb0[nt]),
                                 u3 + ba1[nt], tanhf(v3 + bb1[nt]));
            }
            if (r0 < rows) *(float4*)&out[(size_t)r0 * EMB + c] = o0;
            if (r1 < rows) *(float4*)&out[(size_t)r1 * EMB + c] = o1;
        }
    }
}

// ---- per-step combine: single pass, exp precomputed, a0 cancelled ----
__global__ void k_combine(float* __restrict__ dst, int D, int E) {
    const int e = blockIdx.x;
    const int tid = threadIdx.x;
    __shared__ int js[DMAX];
    if (tid < D) js[tid] = g_idx[e * D + tid];
    __syncthreads();

    float m0 = g_M0[e * EMB + tid];
    float ssum = 0.0f, acc = 0.0f;
    int cnt = 0;
    for (int d = 0; d < D; d++) {
        int j = js[d];
        if (j >= 0) {
            float2 uv = g_UV[j * EMB + tid];
            ssum += uv.x;
            acc  += uv.x * tanhf(m0 + uv.y);
            cnt++;
        }
    }
    dst[e * EMB + tid] = cnt ? (acc / ssum) : tanhf(m0);
}

// ---- segment boundaries (edges sorted by (b,n) key) ----
__global__ void k_segbounds(const int* __restrict__ eb_b, const int* __restrict__ eb_n, int E) {
    int e = blockIdx.x * blockDim.x + threadIdx.x;
    if (e >= E) return;
    int k  = eb_b[e] * VV + eb_n[e];
    int kp = (e == 0) ? -1 : (eb_b[e - 1] * VV + eb_n[e - 1]);
    for (int v = kp + 1; v <= k; v++) g_seg[v] = e;
    if (e == E - 1) for (int v = k + 1; v <= NODES; v++) g_seg[v] = E;
}

// ---- segment sum using precomputed bounds ----
__global__ void k_segsum(const float* __restrict__ mem) {
    const int node = blockIdx.x;
    const int tid = threadIdx.x;
    int lo = g_seg[node], hi = g_seg[node + 1];
    float acc = 0.0f;
    for (int e = lo; e < hi; e++) acc += mem[e * EMB + tid];
    g_gs[node * EMB + tid] = acc;
}

// ---- readout softmax over V nodes + final projection ----
__global__ void k_rsoft(const float* __restrict__ node_mask,
                        const float* __restrict__ W_out, const float* __restrict__ b_out,
                        float* __restrict__ out) {
    const int n = blockIdx.x;
    const int tid = threadIdx.x;
    __shared__ float s_msk[VV];
    __shared__ float ge[EMB];
    __shared__ int   s_any;
    if (tid == 0) s_any = 0;
    __syncthreads();
    if (tid < VV) {
        s_msk[tid] = node_mask[n * VV + tid];
        if (s_msk[tid] > 0.5f) atomicOr(&s_any, 1);
    }
    __syncthreads();
    const int any = s_any;

    const float2* LT = g_UV + (size_t)n * VV * EMB;
    float mx = -1e30f;
    for (int v = 0; v < VV; v++) {
        if (!any || s_msk[v] > 0.5f) {
            float l = LT[v * EMB + tid].x;
            mx = fmaxf(mx, l);
        }
    }
    float ssum = 0.0f, acc = 0.0f;
    for (int v = 0; v < VV; v++) {
        if (!any || s_msk[v] > 0.5f) {
            float2 lt = LT[v * EMB + tid];
            float w = expf(lt.x - mx);
            ssum += w;
            acc  += w * lt.y;
        }
    }
    ge[tid] = acc / ssum;
    __syncthreads();

    float o = b_out[tid];
    #pragma unroll 4
    for (int k = 0; k < EMB; k++) o += ge[k] * W_out[k * EMB + tid];
    out[n * EMB + tid] = o;
}

extern "C" void kernel_launch(void* const* d_in, const int* in_sizes, int n_in,
                              void* d_out, int out_size) {
    const float* nodes     = (const float*)d_in[0];
    const float* edges     = (const float*)d_in[1];
    const float* W_pre     = (const float*)d_in[2];
    const float* b_pre     = (const float*)d_in[3];
    const float* W_att     = (const float*)d_in[4];
    const float* W_emb     = (const float*)d_in[6];
    const float* b_emb     = (const float*)d_in[7];
    const float* Wg_att    = (const float*)d_in[8];
    const float* bg_att    = (const float*)d_in[9];
    const float* Wg_emb    = (const float*)d_in[10];
    const float* bg_emb    = (const float*)d_in[11];
    const float* W_out     = (const float*)d_in[12];
    const float* b_out     = (const float*)d_in[13];
    const float* node_mask = (const float*)d_in[15];
    const int*   eb_b      = (const int*)d_in[16];
    const int*   eb_n      = (const int*)d_in[17];
    const int*   eb_nb     = (const int*)d_in[18];
    const int*   in_eb     = (const int*)d_in[19];
    const int*   in_igeb   = (const int*)d_in[20];
    const int*   in_ige    = (const int*)d_in[21];

    const int E = in_sizes[16];
    const int D = in_sizes[14] / E;
    const int M = in_sizes[19];

    cudaFuncSetAttribute(k_gemm_tc, cudaFuncAttributeMaxDynamicSharedMemorySize, SM_TOTAL);

    float *memA, *memB;
    cudaGetSymbolAddress((void**)&memA, g_mem);
    cudaGetSymbolAddress((void**)&memB, g_memN);
    uint2* bpk;
    cudaGetSymbolAddress((void**)&bpk, g_B);
    float2* uv;
    cudaGetSymbolAddress((void**)&uv, g_UV);
    float* gs;
    cudaGetSymbolAddress((void**)&gs, g_gs);

    k_initidx<<<(E * D + 255) / 256, 256>>>(E * D);
    k_scatter<<<(M + 255) / 256, 256>>>(in_eb, in_igeb, in_ige, M, D);
    k_packb<<<128, 256>>>(W_att, W_emb, Wg_att, Wg_emb);
    k_pre<<<(E + 15) / 16, 128>>>(nodes, edges, W_pre, b_pre, W_emb, b_emb,
                                  eb_b, eb_n, eb_nb, E);

    // step 1 closed-form in k_pre (mem1 = tanh(M0)); run steps 2..3
    float* src = memA;
    float* dst = memB;
    for (int s = 0; s < 2; s++) {
        k_gemm_tc<<<(E + 127) / 128, 256, SM_TOTAL>>>(src, bpk, b_out, b_out, uv, E, 0);
        k_combine<<<E, 128>>>(dst, D, E);
        float* t = src; src = dst; dst = t;
    }

    k_segbounds<<<(E + 255) / 256, 256>>>(eb_b, eb_n, E);
    k_segsum<<<NODES, 128>>>(src);
    k_gemm_tc<<<NODES / 128, 256, SM_TOTAL>>>(gs, bpk + 256 * 64, bg_att, bg_emb, uv, NODES, 1);
    k_rsoft<<<NB, 128>>>(node_mask, W_out, b_out, (float*)d_out);
}

// round 13
// speedup vs baseline: 2.9246x; 1.0336x over previous
#include <cuda_runtime.h>
#include <cuda_bf16.h>
#include <math.h>
#include <stdint.h>

#define NB    512
#define VV    40
#define NODES (NB * VV)      // 20480
#define NF    32
#define EF    4
#define EMB   128
#define BIG_NEG -1000000.0f
#define EMAX  65536
#define DMAX  32

// column-pair index permutation: p = tg + 4h + 8k  ->  j = 2tg + h + 8k
#define PERM(p) ((((p) & 3) << 1) | (((p) >> 2) & 1) | ((p) & ~7))

// ---- scratch (no allocation allowed) ----
__device__ float  g_M0[EMAX * EMB];
__device__ float  g_mem[EMAX * EMB];
__device__ float  g_memN[EMAX * EMB];
__device__ float2 g_UV[EMAX * EMB];     // (expU, V) per edge-ch; (L, tanhT) in readout
__device__ int    g_idx[EMAX * DMAX];
__device__ float  g_gs[NODES * EMB];
__device__ int    g_seg[NODES + 1];
__device__ float  g_P[NODES * 256];     // node projections: [0..127]=n-role, [128..255]=nb-role
// pre-packed B operands, (hi,lo) bf16-pair u64, permuted + XOR-swizzled:
__device__ __align__(16) uint2 g_B[2][256 * 64];   // set0 msg [Wa2|We2], set1 readout
__device__ __align__(16) uint2 g_Bpre[128 * 64];   // W_emb top half (pre stage-2, N=128)
__device__ __align__(16) uint2 g_Bnp[256 * 32];    // W_pre node part (K=32 pad 64, N=256)

__device__ __forceinline__ uint2 pack_hl(float x0, float x1) {
    __nv_bfloat16 h0 = __float2bfloat16(x0);
    __nv_bfloat16 h1 = __float2bfloat16(x1);
    __nv_bfloat16 l0 = __float2bfloat16(x0 - __bfloat162float(h0));
    __nv_bfloat16 l1 = __float2bfloat16(x1 - __bfloat162float(h1));
    uint32_t hi = (uint32_t)*(uint16_t*)&h0 | ((uint32_t)*(uint16_t*)&h1 << 16);
    uint32_t lo = (uint32_t)*(uint16_t*)&l0 | ((uint32_t)*(uint16_t*)&l1 << 16);
    return make_uint2(hi, lo);
}

__device__ __forceinline__ void mma16816(float* d, uint32_t a0, uint32_t a1,
                                         uint32_t a2, uint32_t a3,
                                         uint32_t b0, uint32_t b1) {
    asm volatile("mma.sync.aligned.m16n8k16.row.col.f32.bf16.bf16.f32 "
                 "{%0,%1,%2,%3}, {%4,%5,%6,%7}, {%8,%9}, {%0,%1,%2,%3};"
                 : "+f"(d[0]), "+f"(d[1]), "+f"(d[2]), "+f"(d[3])
                 : "r"(a0), "r"(a1), "r"(a2), "r"(a3), "r"(b0), "r"(b1));
}

// ---- init in-edge index table to -1 ----
__global__ void k_initidx(int n) {
    int i = blockIdx.x * blockDim.x + threadIdx.x;
    if (i < n) g_idx[i] = -1;
}

// ---- scatter in-edge lists ----
__global__ void k_scatter(const int* __restrict__ eb, const int* __restrict__ igeb,
                          const int* __restrict__ ige, int M, int D) {
    int i = blockIdx.x * blockDim.x + threadIdx.x;
    if (i < M) g_idx[igeb[i] * D + ige[i]] = eb[i];
}

// ---- pack all B operands ----
__global__ void k_packb(const float* __restrict__ W_pre,
                        const float* __restrict__ W_att, const float* __restrict__ W_emb,
                        const float* __restrict__ Wg_att, const float* __restrict__ Wg_emb) {
    int idx = blockIdx.x * 256 + threadIdx.x;   // 49152 total
    if (idx < 32768) {
        int set = idx >> 14;
        int rem = idx & 16383;
        int n = rem >> 6, p = rem & 63, kp = 2 * p;
        float x0, x1;
        if (set == 0) {
            if (n < 128) {
                x0 = W_att[(128 + kp) * EMB + n];
                x1 = W_att[(129 + kp) * EMB + n];
            } else {
                x0 = W_emb[(128 + kp) * EMB + (n - 128)];
                x1 = W_emb[(129 + kp) * EMB + (n - 128)];
            }
        } else {
            if (n < 128) {
                x0 = Wg_att[kp * EMB + n]       + Wg_att[(128 + kp) * EMB + n];
                x1 = Wg_att[(kp + 1) * EMB + n] + Wg_att[(129 + kp) * EMB + n];
            } else {
                x0 = Wg_emb[kp * EMB + (n - 128)];
                x1 = Wg_emb[(kp + 1) * EMB + (n - 128)];
            }
        }
        g_B[set][n * 64 + (PERM(p) ^ (4 * (n & 7)))] = pack_hl(x0, x1);
    } else if (idx < 40960) {
        int rem = idx - 32768;                   // W_emb top half, N=128, K=128
        int n = rem >> 6, p = rem & 63, kp = 2 * p;
        float x0 = W_emb[kp * EMB + n];
        float x1 = W_emb[(kp + 1) * EMB + n];
        g_Bpre[n * 64 + (PERM(p) ^ (4 * (n & 7)))] = pack_hl(x0, x1);
    } else {
        int rem = idx - 40960;                   // W_pre node part, N=256, K=32 pad 64
        int n = rem >> 5, p = rem & 31;
        float x0 = 0.f, x1 = 0.f;
        if (p < 16) {
            int kp = 2 * p;
            if (n < 128) {
                x0 = W_pre[kp * EMB + n];
                x1 = W_pre[(kp + 1) * EMB + n];
            } else {
                x0 = W_pre[(32 + kp) * EMB + (n - 128)];
                x1 = W_pre[(33 + kp) * EMB + (n - 128)];
            }
        }
        g_Bnp[n * 32 + (PERM(p) ^ (4 * (n & 7)))] = pack_hl(x0, x1);
    }
}

// ===== node projection: P = nodes[NODES x 32(pad64)] @ Bnp -> [NODES x 256] ====
#define NP_SMB 32768   // Bs [256][32] uint2 -> 64KB? no: 256*32*8 = 65536
#define NP_SMB_BYTES 65536
#define NP_SMA_BYTES 32768   // As [128][32] uint2
#define NP_SM_TOTAL (NP_SMB_BYTES + NP_SMA_BYTES)

__global__ __launch_bounds__(256, 1)
void k_nodeproj_tc(const float* __restrict__ nodes) {
    extern __shared__ __align__(16) char sm[];
    uint2* Bs = (uint2*)sm;                     // [256][32]
    uint2* As = (uint2*)(sm + NP_SMB_BYTES);    // [128][32]
    const int tid = threadIdx.x;
    const int n0 = blockIdx.x * 128;

    {   // copy B: 8192 uint2 = 4096 uint4
        const uint4* s = (const uint4*)g_Bnp;
        uint4* d = (uint4*)Bs;
        #pragma unroll 4
        for (int i = tid; i < 4096; i += 256) d[i] = s[i];
    }
    {   // fill A: row = tid>>1; h=0 -> pairs 0..15 (real), h=1 -> 16..31 (zero)
        int row = tid >> 1, h = tid & 1;
        int sw = 4 * (row & 7);
        uint2* arow = As + row * 32;
        if (h == 0) {
            const float* src = nodes + (size_t)(n0 + row) * NF;
            #pragma unroll
            for (int p = 0; p < 16; p += 2) {
                float4 f = *(const float4*)&src[2 * p];
                arow[PERM(p) ^ sw]     = pack_hl(f.x, f.y);
                arow[PERM(p + 1) ^ sw] = pack_hl(f.z, f.w);
            }
        } else {
            uint2 z = make_uint2(0u, 0u);
            #pragma unroll
            for (int p = 16; p < 32; p++) arow[PERM(p) ^ sw] = z;
        }
    }
    __syncthreads();

    const int wid = tid >> 5, lane = tid & 31;
    const int g = lane >> 2, tg = lane & 3;
    const int nU = wid * 16;

    #pragma unroll 1
    for (int mt = 0; mt < 8; mt++) {
        float d[4][4];
        #pragma unroll
        for (int a = 0; a < 4; a++)
            #pragma unroll
            for (int b = 0; b < 4; b++) d[a][b] = 0.0f;
        const int rowA = mt * 16 + g;
        #pragma unroll
        for (int k = 0; k < 4; k++) {
            int jx = (2 * tg + 8 * k) ^ (4 * g);
            uint4 A1 = *(const uint4*)&As[rowA * 32 + jx];
            uint4 A2 = *(const uint4*)&As[(rowA + 8) * 32 + jx];
            #pragma unroll
            for (int nt = 0; nt < 4; nt++) {
                int nr = (nt < 2) ? (nU + nt * 8) : (128 + nU + (nt - 2) * 8);
                uint4 Bf = *(const uint4*)&Bs[(nr + g) * 32 + jx];
                mma16816(d[nt], A1.x, A2.x, A1.z, A2.z, Bf.x, Bf.z);
                mma16816(d[nt], A1.x, A2.x, A1.z, A2.z, Bf.y, Bf.w);
                mma16816(d[nt], A1.y, A2.y, A1.w, A2.w, Bf.x, Bf.z);
            }
        }
        int r0 = n0 + mt * 16 + g, r1 = r0 + 8;
        #pragma unroll
        for (int nt = 0; nt < 4; nt++) {
            int cc = (nt < 2) ? (nU + nt * 8 + tg * 2) : (128 + nU + (nt - 2) * 8 + tg * 2);
            *(float2*)&g_P[(size_t)r0 * 256 + cc] = make_float2(d[nt][0], d[nt][1]);
            *(float2*)&g_P[(size_t)r1 * 256 + cc] = make_float2(d[nt][2], d[nt][3]);
        }
    }
}

// ===== fused pre: e_emb = tanh(P1+P2+edge_term+b_pre); M0 = e_emb @ Wemb_top + b_emb;
//       mem1 = tanh(M0)  (step-1 closed form) =====
#define PR_SMB_BYTES 65536    // Bs [128][64] uint2
#define PR_SMA_BYTES 65536    // As [128][64] uint2
#define PR_SMX_BYTES 8192     // s_bn/s_bnb/s_ed/wp/biases
#define PR_SM_TOTAL (PR_SMB_BYTES + PR_SMA_BYTES + PR_SMX_BYTES)

__global__ __launch_bounds__(256, 1)
void k_pre_tc(const float* __restrict__ edges,
              const float* __restrict__ W_pre, const float* __restrict__ b_pre,
              const float* __restrict__ b_emb,
              const int* __restrict__ eb_b, const int* __restrict__ eb_n,
              const int* __restrict__ eb_nb, int E) {
    extern __shared__ __align__(16) char sm[];
    uint2*  Bs   = (uint2*)sm;                            // [128][64]
    uint2*  As   = (uint2*)(sm + PR_SMB_BYTES);           // [128][64]
    char*   xtra = sm + PR_SMB_BYTES + PR_SMA_BYTES;
    int*    s_bn  = (int*)xtra;                           // [128]
    int*    s_bnb = (int*)(xtra + 512);                   // [128]
    float4* s_ed  = (float4*)(xtra + 1024);               // [128]
    float*  s_wp0 = (float*)(xtra + 3072);                // [128] x 4 rows
    float*  s_wp1 = s_wp0 + 128;
    float*  s_wp2 = s_wp0 + 256;
    float*  s_wp3 = s_wp0 + 384;
    float*  s_bp  = s_wp0 + 512;                          // b_pre
    float*  s_be  = s_wp0 + 640;                          // b_emb

    const int tid = threadIdx.x;
    const int e0 = blockIdx.x * 128;

    {   // copy B (W_emb top): 8192 uint2 = 4096 uint4
        const uint4* s = (const uint4*)g_Bpre;
        uint4* d = (uint4*)Bs;
        #pragma unroll 4
        for (int i = tid; i < 4096; i += 256) d[i] = s[i];
    }
    if (tid < 128) {
        s_wp0[tid] = W_pre[64 * EMB + tid];
        s_wp1[tid] = W_pre[65 * EMB + tid];
        s_wp2[tid] = W_pre[66 * EMB + tid];
        s_wp3[tid] = W_pre[67 * EMB + tid];
        s_bp[tid]  = b_pre[tid];
        s_be[tid]  = b_emb[tid];
        int e = e0 + tid;
        if (e < E) {
            int b = eb_b[e], n = eb_n[e], nb = eb_nb[e];
            s_bn[tid]  = (b * VV + n) * 256;
            s_bnb[tid] = (b * VV + nb) * 256 + 128;
            s_ed[tid]  = *(const float4*)&edges[(size_t)((b * VV + n) * VV + nb) * EF];
        } else {
            s_bn[tid] = -1;
        }
    }
    __syncthreads();

    // phase 1: each warp computes e_emb for 16 edges, 4 channels/lane, packs into As
    {
        const int wid = tid >> 5, lane = tid & 31;
        #pragma unroll 1
        for (int it = 0; it < 16; it++) {
            int r = wid * 16 + it;
            int sw = 4 * (r & 7);
            uint2* arow = As + r * 64;
            int p0 = 2 * lane;
            if (s_bn[r] >= 0) {
                float4 f1 = *(const float4*)&g_P[(size_t)s_bn[r]  + 4 * lane];
                float4 f2 = *(const float4*)&g_P[(size_t)s_bnb[r] + 4 * lane];
                float4 ed = s_ed[r];
                int c = 4 * lane;
                float4 w0 = *(const float4*)&s_wp0[c];
                float4 w1 = *(const float4*)&s_wp1[c];
                float4 w2 = *(const float4*)&s_wp2[c];
                float4 w3 = *(const float4*)&s_wp3[c];
                float4 bp = *(const float4*)&s_bp[c];
                float e0v = tanhf(f1.x + f2.x + ed.x * w0.x + ed.y * w1.x + ed.z * w2.x + ed.w * w3.x + bp.x);
                float e1v = tanhf(f1.y + f2.y + ed.x * w0.y + ed.y * w1.y + ed.z * w2.y + ed.w * w3.y + bp.y);
                float e2v = tanhf(f1.z + f2.z + ed.x * w0.z + ed.y * w1.z + ed.z * w2.z + ed.w * w3.z + bp.z);
                float e3v = tanhf(f1.w + f2.w + ed.x * w0.w + ed.y * w1.w + ed.z * w2.w + ed.w * w3.w + bp.w);
                arow[PERM(p0) ^ sw]     = pack_hl(e0v, e1v);
                arow[PERM(p0 + 1) ^ sw] = pack_hl(e2v, e3v);
            } else {
                uint2 z = make_uint2(0u, 0u);
                arow[PERM(p0) ^ sw]     = z;
                arow[PERM(p0 + 1) ^ sw] = z;
            }
        }
    }
    __syncthreads();

    // phase 2: MMA 128x128x128 -> M0, mem1
    const int wid = tid >> 5, lane = tid & 31;
    const int g = lane >> 2, tg = lane & 3;
    const int nU = wid * 16;

    #pragma unroll 1
    for (int mt = 0; mt < 8; mt++) {
        float d[2][4];
        #pragma unroll
        for (int a = 0; a < 2; a++)
            #pragma unroll
            for (int b = 0; b < 4; b++) d[a][b] = 0.0f;
        const int rowA = mt * 16 + g;
        #pragma unroll 1
        for (int k = 0; k < 8; k++) {
            int jx = (2 * tg + 8 * k) ^ (4 * g);
            uint4 A1 = *(const uint4*)&As[rowA * 64 + jx];
            uint4 A2 = *(const uint4*)&As[(rowA + 8) * 64 + jx];
            #pragma unroll
            for (int nt = 0; nt < 2; nt++) {
                uint4 Bf = *(const uint4*)&Bs[(nU + nt * 8 + g) * 64 + jx];
                mma16816(d[nt], A1.x, A2.x, A1.z, A2.z, Bf.x, Bf.z);
                mma16816(d[nt], A1.x, A2.x, A1.z, A2.z, Bf.y, Bf.w);
                mma16816(d[nt], A1.y, A2.y, A1.w, A2.w, Bf.x, Bf.z);
            }
        }
        int r0 = e0 + mt * 16 + g, r1 = r0 + 8;
        #pragma unroll
        for (int nt = 0; nt < 2; nt++) {
            int c = nU + nt * 8 + tg * 2;
            float be0 = s_be[c], be1 = s_be[c + 1];
            float m00 = d[nt][0] + be0, m01 = d[nt][1] + be1;
            float m10 = d[nt][2] + be0, m11 = d[nt][3] + be1;
            if (r0 < E) {
                *(float2*)&g_M0[(size_t)r0 * EMB + c]  = make_float2(m00, m01);
                *(float2*)&g_mem[(size_t)r0 * EMB + c] = make_float2(tanhf(m00), tanhf(m01));
            }
            if (r1 < E) {
                *(float2*)&g_M0[(size_t)r1 * EMB + c]  = make_float2(m10, m11);
                *(float2*)&g_mem[(size_t)r1 * EMB + c] = make_float2(tanhf(m10), tanhf(m11));
            }
        }
    }
}

// ============ tensor-core GEMM: [rows x 128] @ [128 x 256] (split bf16) ======
#define SMB_BYTES 131072      // B: [256][64] uint2
#define SMA_BYTES 65536       // A: [128][64] uint2
#define SM_TOTAL  (SMB_BYTES + SMA_BYTES)

__global__ __launch_bounds__(256, 1)
void k_gemm_tc(const float* __restrict__ src, const uint2* __restrict__ Bg,
               const float* __restrict__ ba, const float* __restrict__ bb,
               float2* __restrict__ out, int rows, int mode) {
    extern __shared__ __align__(16) char sm[];
    uint2* Bs = (uint2*)sm;                       // [256][64]
    uint2* As = (uint2*)(sm + SMB_BYTES);         // [128][64]
    const int tid = threadIdx.x;
    const int e0 = blockIdx.x * 128;

    {
        const uint4* s = (const uint4*)Bg;
        uint4* d = (uint4*)Bs;
        #pragma unroll 4
        for (int i = tid; i < 8192; i += 256) d[i] = s[i];
    }
    {
        int row = tid >> 1, half = tid & 1;
        int e = e0 + row;
        int sw = 4 * (row & 7);
        uint2* arow = As + row * 64;
        #pragma unroll 1
        for (int p = half * 32; p < half * 32 + 32; p += 2) {
            float4 f = make_float4(0.f, 0.f, 0.f, 0.f);
            if (e < rows) f = *(const float4*)&src[e * EMB + 2 * p];
            arow[PERM(p) ^ sw]     = pack_hl(f.x, f.y);
            arow[PERM(p + 1) ^ sw] = pack_hl(f.z, f.w);
        }
    }
    __syncthreads();

    const int wid = tid >> 5, lane = tid & 31;
    const int g = lane >> 2, tg = lane & 3;
    const int nU = wid * 16;

    float ba0[2], ba1[2], bb0[2], bb1[2];
    if (mode == 1) {
        #pragma unroll
        for (int nt = 0; nt < 2; nt++) {
            int c = nU + nt * 8 + tg * 2;
            ba0[nt] = ba[c]; ba1[nt] = ba[c + 1];
            bb0[nt] = bb[c]; bb1[nt] = bb[c + 1];
        }
    }

    #pragma unroll 1
    for (int mt = 0; mt < 8; mt++) {
        float d[4][4];
        #pragma unroll
        for (int a = 0; a < 4; a++)
            #pragma unroll
            for (int b = 0; b < 4; b++) d[a][b] = 0.0f;

        const int rowA = mt * 16 + g;
        #pragma unroll 1
        for (int k = 0; k < 8; k++) {
            int jx = (2 * tg + 8 * k) ^ (4 * g);
            uint4 A1 = *(const uint4*)&As[rowA * 64 + jx];
            uint4 A2 = *(const uint4*)&As[(rowA + 8) * 64 + jx];
            #pragma unroll
            for (int nt = 0; nt < 4; nt++) {
                int n0 = (nt < 2) ? (nU + nt * 8) : (128 + nU + (nt - 2) * 8);
                uint4 Bf = *(const uint4*)&Bs[(n0 + g) * 64 + jx];
                mma16816(d[nt], A1.x, A2.x, A1.z, A2.z, Bf.x, Bf.z);
                mma16816(d[nt], A1.x, A2.x, A1.z, A2.z, Bf.y, Bf.w);
                mma16816(d[nt], A1.y, A2.y, A1.w, A2.w, Bf.x, Bf.z);
            }
        }

        int r0 = e0 + mt * 16 + g, r1 = r0 + 8;
        #pragma unroll
        for (int nt = 0; nt < 2; nt++) {
            int c = nU + nt * 8 + tg * 2;
            float u0 = d[nt][0], u1 = d[nt][1], u2 = d[nt][2], u3 = d[nt][3];
            float v0 = d[nt + 2][0], v1 = d[nt + 2][1], v2 = d[nt + 2][2], v3 = d[nt + 2][3];
            float4 o0, o1;
            if (mode == 0) {
                o0 = make_float4(expf(u0), v0, expf(u1), v1);
                o1 = make_float4(expf(u2), v2, expf(u3), v3);
            } else {
                o0 = make_float4(u0 + ba0[nt], tanhf(v0 + bb0[nt]),
                                 u1 + ba1[nt], tanhf(v1 + bb1[nt]));
                o1 = make_float4(u2 + ba0[nt], tanhf(v2 + bb0[nt]),
                                 u3 + ba1[nt], tanhf(v3 + bb1[nt]));
            }
            if (r0 < rows) *(float4*)&out[(size_t)r0 * EMB + c] = o0;
            if (r1 < rows) *(float4*)&out[(size_t)r1 * EMB + c] = o1;
        }
    }
}

// ---- per-step combine ----
__global__ void k_combine(float* __restrict__ dst, int D, int E) {
    const int e = blockIdx.x;
    const int tid = threadIdx.x;
    __shared__ int js[DMAX];
    if (tid < D) js[tid] = g_idx[e * D + tid];
    __syncthreads();

    float m0 = g_M0[e * EMB + tid];
    float ssum = 0.0f, acc = 0.0f;
    int cnt = 0;
    for (int d = 0; d < D; d++) {
        int j = js[d];
        if (j >= 0) {
            float2 uv = g_UV[j * EMB + tid];
            ssum += uv.x;
            acc  += uv.x * tanhf(m0 + uv.y);
            cnt++;
        }
    }
    dst[e * EMB + tid] = cnt ? (acc / ssum) : tanhf(m0);
}

// ---- segment boundaries ----
__global__ void k_segbounds(const int* __restrict__ eb_b, const int* __restrict__ eb_n, int E) {
    int e = blockIdx.x * blockDim.x + threadIdx.x;
    if (e >= E) return;
    int k  = eb_b[e] * VV + eb_n[e];
    int kp = (e == 0) ? -1 : (eb_b[e - 1] * VV + eb_n[e - 1]);
    for (int v = kp + 1; v <= k; v++) g_seg[v] = e;
    if (e == E - 1) for (int v = k + 1; v <= NODES; v++) g_seg[v] = E;
}

// ---- segment sum ----
__global__ void k_segsum(const float* __restrict__ mem) {
    const int node = blockIdx.x;
    const int tid = threadIdx.x;
    int lo = g_seg[node], hi = g_seg[node + 1];
    float acc = 0.0f;
    for (int e = lo; e < hi; e++) acc += mem[e * EMB + tid];
    g_gs[node * EMB + tid] = acc;
}

// ---- readout softmax + final projection ----
__global__ void k_rsoft(const float* __restrict__ node_mask,
                        const float* __restrict__ W_out, const float* __restrict__ b_out,
                        float* __restrict__ out) {
    const int n = blockIdx.x;
    const int tid = threadIdx.x;
    __shared__ float s_msk[VV];
    __shared__ float ge[EMB];
    __shared__ int   s_any;
    if (tid == 0) s_any = 0;
    __syncthreads();
    if (tid < VV) {
        s_msk[tid] = node_mask[n * VV + tid];
        if (s_msk[tid] > 0.5f) atomicOr(&s_any, 1);
    }
    __syncthreads();
    const int any = s_any;

    const float2* LT = g_UV + (size_t)n * VV * EMB;
    float mx = -1e30f;
    for (int v = 0; v < VV; v++) {
        if (!any || s_msk[v] > 0.5f) {
            float l = LT[v * EMB + tid].x;
            mx = fmaxf(mx, l);
        }
    }
    float ssum = 0.0f, acc = 0.0f;
    for (int v = 0; v < VV; v++) {
        if (!any || s_msk[v] > 0.5f) {
            float2 lt = LT[v * EMB + tid];
            float w = expf(lt.x - mx);
            ssum += w;
            acc  += w * lt.y;
        }
    }
    ge[tid] = acc / ssum;
    __syncthreads();

    float o = b_out[tid];
    #pragma unroll 4
    for (int k = 0; k < EMB; k++) o += ge[k] * W_out[k * EMB + tid];
    out[n * EMB + tid] = o;
}

extern "C" void kernel_launch(void* const* d_in, const int* in_sizes, int n_in,
                              void* d_out, int out_size) {
    const float* nodes     = (const float*)d_in[0];
    const float* edges     = (const float*)d_in[1];
    const float* W_pre     = (const float*)d_in[2];
    const float* b_pre     = (const float*)d_in[3];
    const float* W_att     = (const float*)d_in[4];
    const float* W_emb     = (const float*)d_in[6];
    const float* b_emb     = (const float*)d_in[7];
    const float* Wg_att    = (const float*)d_in[8];
    const float* bg_att    = (const float*)d_in[9];
    const float* Wg_emb    = (const float*)d_in[10];
    const float* bg_emb    = (const float*)d_in[11];
    const float* W_out     = (const float*)d_in[12];
    const float* b_out     = (const float*)d_in[13];
    const float* node_mask = (const float*)d_in[15];
    const int*   eb_b      = (const int*)d_in[16];
    const int*   eb_n      = (const int*)d_in[17];
    const int*   eb_nb     = (const int*)d_in[18];
    const int*   in_eb     = (const int*)d_in[19];
    const int*   in_igeb   = (const int*)d_in[20];
    const int*   in_ige    = (const int*)d_in[21];

    const int E = in_sizes[16];
    const int D = in_sizes[14] / E;
    const int M = in_sizes[19];

    cudaFuncSetAttribute(k_gemm_tc, cudaFuncAttributeMaxDynamicSharedMemorySize, SM_TOTAL);
    cudaFuncSetAttribute(k_pre_tc, cudaFuncAttributeMaxDynamicSharedMemorySize, PR_SM_TOTAL);
    cudaFuncSetAttribute(k_nodeproj_tc, cudaFuncAttributeMaxDynamicSharedMemorySize, NP_SM_TOTAL);

    float *memA, *memB;
    cudaGetSymbolAddress((void**)&memA, g_mem);
    cudaGetSymbolAddress((void**)&memB, g_memN);
    uint2* bpk;
    cudaGetSymbolAddress((void**)&bpk, g_B);
    float2* uv;
    cudaGetSymbolAddress((void**)&uv, g_UV);
    float* gs;
    cudaGetSymbolAddress((void**)&gs, g_gs);

    k_initidx<<<(E * D + 255) / 256, 256>>>(E * D);
    k_scatter<<<(M + 255) / 256, 256>>>(in_eb, in_igeb, in_ige, M, D);
    k_packb<<<192, 256>>>(W_pre, W_att, W_emb, Wg_att, Wg_emb);
    k_nodeproj_tc<<<NODES / 128, 256, NP_SM_TOTAL>>>(nodes);
    k_pre_tc<<<(E + 127) / 128, 256, PR_SM_TOTAL>>>(edges, W_pre, b_pre, b_emb,
                                                    eb_b, eb_n, eb_nb, E);

    // step 1 closed-form (mem1 = tanh(M0)); run steps 2..3
    float* src = memA;
    float* dst = memB;
    for (int s = 0; s < 2; s++) {
        k_gemm_tc<<<(E + 127) / 128, 256, SM_TOTAL>>>(src, bpk, b_out, b_out, uv, E, 0);
        k_combine<<<E, 128>>>(dst, D, E);
        float* t = src; src = dst; dst = t;
    }

    k_segbounds<<<(E + 255) / 256, 256>>>(eb_b, eb_n, E);
    k_segsum<<<NODES, 128>>>(src);
    k_gemm_tc<<<NODES / 128, 256, SM_TOTAL>>>(gs, bpk + 256 * 64, bg_att, bg_emb, uv, NODES, 1);
    k_rsoft<<<NB, 128>>>(node_mask, W_out, b_out, (float*)d_out);
}